// round 7
// baseline (speedup 1.0000x reference)
#include <cuda_runtime.h>

// Sizes (fixed by the problem)
#define BB   32
#define TT   128
#define INN  128
#define HH   256
#define G4   1024   // 4*HH
#define OO   128

// ---------------- scratch (__device__ globals: no runtime allocation) -------
// NOTE: __align__(16) is load-bearing — these are accessed via ulonglong2*
// (16-byte LDG/LDS); a misaligned wide op is a HW trap (err715) on sm_103a.
static __device__ __align__(16) float g_xg[BB * TT * G4];   // xg = x@W_ih^T + b_ih + b_hh
static __device__ __align__(16) float g_bx[BB * TT * HH];   // Bx = x@W_B^T + b_B
static __device__ __align__(16) float g_whh_p[G4 * HH];     // W_hh repacked (coalesced)
static __device__ __align__(16) float g_wa_p[HH * HH];      // W_A repacked (row=tid>>2, quarter=tid&3)
static __device__ __align__(16) float g_wc_p[OO * HH];      // W_C repacked (row=tid>>3, eighth=tid&7)

typedef unsigned long long ull;

__device__ __forceinline__ ull ffma2(ull c, ull a, ull b) {
    ull d;
    asm("fma.rn.f32x2 %0, %1, %2, %3;" : "=l"(d) : "l"(a), "l"(b), "l"(c));
    return d;
}
__device__ __forceinline__ float hsum2(ull v) {
    return __uint_as_float((unsigned)(v & 0xffffffffull)) +
           __uint_as_float((unsigned)(v >> 32));
}

// ---------------- precompute GEMMs: C[4096,N] = X[4096,128] @ W[N,128]^T + bias (+bias2)
template <int N, int DEST>
__global__ __launch_bounds__(256) void gemm_bias(
    const float* __restrict__ X, const float* __restrict__ W,
    const float* __restrict__ bias, const float* __restrict__ bias2)
{
    constexpr int K = INN;  // 128
    __shared__ float As[32][64];  // k-major
    __shared__ float Bs[32][64];
    float* C = (DEST == 0) ? g_xg : g_bx;

    const int bm = blockIdx.y * 64, bn = blockIdx.x * 64;
    const int tid = threadIdx.x;
    const int tx = tid & 15, ty = tid >> 4;

    float acc[4][4];
#pragma unroll
    for (int r = 0; r < 4; r++)
#pragma unroll
        for (int c = 0; c < 4; c++) acc[r][c] = 0.f;

    for (int k0 = 0; k0 < K; k0 += 32) {
#pragma unroll
        for (int q = 0; q < 2; q++) {
            int i = tid * 2 + q;          // 0..511
            int row = i >> 3;             // 0..63
            int kc = (i & 7) * 4;         // 0..28
            float4 a = *(const float4*)(X + (size_t)(bm + row) * K + k0 + kc);
            As[kc + 0][row] = a.x; As[kc + 1][row] = a.y;
            As[kc + 2][row] = a.z; As[kc + 3][row] = a.w;
            float4 b = *(const float4*)(W + (size_t)(bn + row) * K + k0 + kc);
            Bs[kc + 0][row] = b.x; Bs[kc + 1][row] = b.y;
            Bs[kc + 2][row] = b.z; Bs[kc + 3][row] = b.w;
        }
        __syncthreads();
#pragma unroll
        for (int kk = 0; kk < 32; kk++) {
            float4 av = *(const float4*)&As[kk][ty * 4];
            float4 bv = *(const float4*)&Bs[kk][tx * 4];
            float ar[4] = {av.x, av.y, av.z, av.w};
            float br[4] = {bv.x, bv.y, bv.z, bv.w};
#pragma unroll
            for (int r = 0; r < 4; r++)
#pragma unroll
                for (int c = 0; c < 4; c++) acc[r][c] += ar[r] * br[c];
        }
        __syncthreads();
    }

    float bc[4];
#pragma unroll
    for (int c = 0; c < 4; c++) {
        bc[c] = bias[bn + tx * 4 + c];
        if (bias2) bc[c] += bias2[bn + tx * 4 + c];
    }
#pragma unroll
    for (int r = 0; r < 4; r++) {
        float4 o;
        o.x = acc[r][0] + bc[0]; o.y = acc[r][1] + bc[1];
        o.z = acc[r][2] + bc[2]; o.w = acc[r][3] + bc[3];
        *(float4*)(C + (size_t)(bm + ty * 4 + r) * N + bn + tx * 4) = o;
    }
}

// ---------------- weight repack for coalesced recurrent loads ---------------
// g_whh_p[(k4*1024 + g)*4 + m] = W_hh[g*256 + 4*k4 + m]               (k4: 0..63)
// g_wa_p [(k *1024 + t)*4 + m] = W_A [(t>>2)*256 + (t&3)*64 + 4k + m] (k: 0..15)
// g_wc_p [(k *1024 + t)*4 + m] = W_C [(t>>3)*256 + (t&7)*32 + 4k + m] (k: 0..7)
__global__ void pack_weights(const float* __restrict__ W_hh,
                             const float* __restrict__ W_A,
                             const float* __restrict__ W_C)
{
    int i = blockIdx.x * blockDim.x + threadIdx.x;
    if (i < G4 * HH) {
        int m = i & 3, gk = i >> 2;
        int g = gk & 1023, k4 = gk >> 10;
        g_whh_p[i] = W_hh[g * HH + k4 * 4 + m];
    }
    if (i < HH * HH) {
        int m = i & 3, kt = i >> 2;
        int tp = kt & 1023, k = kt >> 10;
        g_wa_p[i] = W_A[(tp >> 2) * HH + (tp & 3) * 64 + k * 4 + m];
    }
    if (i < OO * HH) {
        int m = i & 3, kt = i >> 2;
        int tp = kt & 1023, k = kt >> 10;
        g_wc_p[i] = W_C[(tp >> 3) * HH + (tp & 7) * 32 + k * 4 + m];
    }
}

// ---------------- sequential fused LSTM + CfC kernel: 1 CTA per batch -------
__global__ __launch_bounds__(1024, 1) void seq_kernel(
    const float* __restrict__ timespans,  // [B,T]
    const float* __restrict__ tau,        // [H]
    const float* __restrict__ sigma,      // [H]
    const float* __restrict__ b_C,        // [OUT]
    float* __restrict__ out)              // [B,T,OUT]
{
    __shared__ __align__(16) float sh_h[HH];     // LSTM hidden
    __shared__ __align__(16) float sh_u[HH];     // ODE state
    __shared__ __align__(16) float sh_us[HH];    // u / tau
    __shared__ __align__(16) float sh_fu[HH];    // tanh(u / sigma)
    __shared__ __align__(16) float sh_g[G4];     // gate pre-activations
    __shared__ __align__(16) float sh_v1[HH];    // ts * A_eff @ u
    __shared__ __align__(16) float sh_v1s[HH];   // v1 / tau
    __shared__ __align__(16) float sh_drv[HH];   // W_A @ f_u
    __shared__ __align__(16) float sh_v2[HH];    // A_eff @ v1
    __shared__ __align__(16) float sh_itau[HH];
    __shared__ __align__(16) float sh_isig[HH];

    const int b = blockIdx.x;
    const int tid = threadIdx.x;

    if (tid < HH) {
        sh_h[tid] = 0.f; sh_u[tid] = 0.f; sh_us[tid] = 0.f; sh_fu[tid] = 0.f;
        sh_itau[tid] = 1.0f / tau[tid];
        sh_isig[tid] = 1.0f / sigma[tid];
    }
    float c_st = 0.f;
    __syncthreads();

    const int r4 = tid >> 2, q4 = tid & 3;   // W_A row / quarter of j-range
    const int r8 = tid >> 3, q8 = tid & 7;   // W_C row / eighth of j-range
    const float it_r = sh_itau[r4];
    const float bCr  = b_C[r8];

    const ulonglong2* whh = (const ulonglong2*)g_whh_p + tid;
    const ulonglong2* wap = (const ulonglong2*)g_wa_p + tid;
    const ulonglong2* wcp = (const ulonglong2*)g_wc_p + tid;
    const ulonglong2* hh2 = (const ulonglong2*)sh_h;
    const ulonglong2* us2 = (const ulonglong2*)(sh_us + (q4 << 6));
    const ulonglong2* fu2 = (const ulonglong2*)(sh_fu + (q4 << 6));
    const ulonglong2* v1s2 = (const ulonglong2*)(sh_v1s + (q4 << 6));
    const ulonglong2* uu2 = (const ulonglong2*)(sh_u + (q8 << 5));

    const float* xg_b = g_xg + (size_t)b * TT * G4 + tid;
    const float* bx_b = g_bx + (size_t)b * TT * HH + tid;
    const float* ts_b = timespans + b * TT;
    float* out_b = out + (size_t)b * TT * OO;

    for (int t = 0; t < TT; t++) {
        const float ts = ts_b[t];

        // -------- Phase A: gate pre-activations (all 1024 threads, 1 row each)
        {
            ull a0 = 0ull, a1 = 0ull;
#pragma unroll 4
            for (int k = 0; k < 64; k++) {
                ulonglong2 wv = whh[k * 1024];   // coalesced LDG.128
                ulonglong2 hv = hh2[k];          // broadcast LDS.128
                a0 = ffma2(a0, wv.x, hv.x);
                a1 = ffma2(a1, wv.y, hv.y);
            }
            sh_g[tid] = xg_b[(size_t)t * G4] + hsum2(a0) + hsum2(a1);
        }
        // -------- Phase A2: v1 = ts*A_eff@u and drive = W_A@f_u (shared weight read)
        {
            ull av = 0ull, ad = 0ull;
#pragma unroll
            for (int k = 0; k < 16; k++) {
                ulonglong2 wv = wap[k * 1024];
                ulonglong2 uv = us2[k];
                ulonglong2 fv = fu2[k];
                av = ffma2(av, wv.x, uv.x); av = ffma2(av, wv.y, uv.y);
                ad = ffma2(ad, wv.x, fv.x); ad = ffma2(ad, wv.y, fv.y);
            }
            float v = hsum2(av), d = hsum2(ad);
            v += __shfl_down_sync(0xffffffffu, v, 2, 4);
            v += __shfl_down_sync(0xffffffffu, v, 1, 4);
            d += __shfl_down_sync(0xffffffffu, d, 2, 4);
            d += __shfl_down_sync(0xffffffffu, d, 1, 4);
            if (q4 == 0) {
                float vv = ts * v;
                sh_v1[r4] = vv;
                sh_v1s[r4] = vv * it_r;
                sh_drv[r4] = d;
            }
        }
        __syncthreads();

        // -------- Phase B: LSTM cell update (tid<256) + v2 = A_eff@v1 (all)
        float bb = 0.f;
        if (tid < HH) {
            float gi = sh_g[tid];
            float gf = sh_g[HH + tid];
            float gg = sh_g[2 * HH + tid];
            float go = sh_g[3 * HH + tid];
            float si = 1.f / (1.f + __expf(-gi));
            float sf = 1.f / (1.f + __expf(-gf));
            float so = 1.f / (1.f + __expf(-go));
            c_st = sf * c_st + si * tanhf(gg);
            bb = so * tanhf(c_st);
            sh_h[tid] = bb;
        }
        {
            ull av = 0ull;
#pragma unroll
            for (int k = 0; k < 16; k++) {
                ulonglong2 wv = wap[k * 1024];
                ulonglong2 xv = v1s2[k];
                av = ffma2(av, wv.x, xv.x);
                av = ffma2(av, wv.y, xv.y);
            }
            float v = hsum2(av);
            v += __shfl_down_sync(0xffffffffu, v, 2, 4);
            v += __shfl_down_sync(0xffffffffu, v, 1, 4);
            if (q4 == 0) sh_v2[r4] = v;
        }
        __syncthreads();

        // -------- Phase C: ODE state update (tid<256)
        if (tid < HH) {
            float bx = bx_b[(size_t)t * HH];
            float un = sh_u[tid] + sh_v1[tid] + 0.5f * ts * sh_v2[tid]
                     + ts * (sh_drv[tid] + bx) * sh_itau[tid] + bb;
            sh_u[tid] = un;
            sh_us[tid] = un * sh_itau[tid];
            sh_fu[tid] = tanhf(un * sh_isig[tid]);
        }
        __syncthreads();

        // -------- Phase D: y = u_new @ W_C^T + b_C  (128 rows x 8 lanes)
        {
            ull ay = 0ull;
#pragma unroll
            for (int k = 0; k < 8; k++) {
                ulonglong2 wv = wcp[k * 1024];
                ulonglong2 uv = uu2[k];
                ay = ffma2(ay, wv.x, uv.x);
                ay = ffma2(ay, wv.y, uv.y);
            }
            float y = hsum2(ay);
            y += __shfl_down_sync(0xffffffffu, y, 4, 8);
            y += __shfl_down_sync(0xffffffffu, y, 2, 8);
            y += __shfl_down_sync(0xffffffffu, y, 1, 8);
            if (q8 == 0) out_b[(size_t)t * OO + r8] = y + bCr;
        }
        // no sync needed here: next Phase A writes only sh_g/sh_v1* (whose
        // prior-iteration readers are upstream of sync #3) and reads
        // sh_h/sh_us/sh_fu (synced above). Phase D's sh_u reads are protected
        // by sync #2 of the next iteration preceding Phase C's sh_u writes.
    }
}

// ---------------- launch ----------------------------------------------------
extern "C" void kernel_launch(void* const* d_in, const int* in_sizes, int n_in,
                              void* d_out, int out_size)
{
    const float* x    = (const float*)d_in[0];   // [32,128,128]
    const float* tsp  = (const float*)d_in[1];   // [32,128]
    const float* tau  = (const float*)d_in[2];   // [256]
    const float* sig  = (const float*)d_in[3];   // [256]
    const float* W_A  = (const float*)d_in[4];   // [256,256]
    const float* W_B  = (const float*)d_in[5];   // [256,128]
    const float* b_B  = (const float*)d_in[6];   // [256]
    const float* W_C  = (const float*)d_in[7];   // [128,256]
    const float* b_C  = (const float*)d_in[8];   // [128]
    const float* W_ih = (const float*)d_in[9];   // [1024,128]
    const float* W_hh = (const float*)d_in[10];  // [1024,256]
    const float* b_ih = (const float*)d_in[11];  // [1024]
    const float* b_hh = (const float*)d_in[12];  // [1024]
    float* out = (float*)d_out;                  // [32,128,128]

    // weight repack (recomputed every call: deterministic, graph-capturable)
    pack_weights<<<(G4 * HH + 255) / 256, 256>>>(W_hh, W_A, W_C);

    // xg = x @ W_ih^T + b_ih + b_hh ; Bx = x @ W_B^T + b_B
    gemm_bias<G4, 0><<<dim3(G4 / 64, (BB * TT) / 64), 256>>>(x, W_ih, b_ih, b_hh);
    gemm_bias<HH, 1><<<dim3(HH / 64, (BB * TT) / 64), 256>>>(x, W_B, b_B, nullptr);

    // sequential fused LSTM + closed-form-continuous recurrence
    seq_kernel<<<BB, 1024>>>(tsp, tau, sig, b_C, out);
}

// round 8
// speedup vs baseline: 1.9475x; 1.9475x over previous
#include <cuda_runtime.h>
#include <cstdint>

// Sizes (fixed by the problem)
#define BB   32
#define TT   128
#define INN  128
#define HH   256
#define G4   1024   // 4*HH
#define OO   128

// ---------------- scratch (__device__ globals: no runtime allocation) -------
static __device__ __align__(16) float g_xg[BB * TT * G4];   // xg = x@W_ih^T + b_ih + b_hh
static __device__ __align__(16) float g_bx[BB * TT * HH];   // Bx = x@W_B^T + b_B
static __device__ __align__(16) float g_whh_p[G4 * HH];     // W_hh repacked (4-way split)
static __device__ __align__(16) float g_wa_p[HH * HH];      // W_A repacked
static __device__ __align__(16) float g_wc_p[OO * HH];      // W_C repacked

typedef unsigned long long ull;

__device__ __forceinline__ ull ffma2(ull c, ull a, ull b) {
    ull d;
    asm("fma.rn.f32x2 %0, %1, %2, %3;" : "=l"(d) : "l"(a), "l"(b), "l"(c));
    return d;
}
__device__ __forceinline__ float hsum2(ull v) {
    return __uint_as_float((unsigned)(v & 0xffffffffull)) +
           __uint_as_float((unsigned)(v >> 32));
}
__device__ __forceinline__ uint32_t s2u(const void* p) {
    uint32_t a;
    asm("{ .reg .u64 t; cvta.to.shared.u64 t, %1; cvt.u32.u64 %0, t; }"
        : "=r"(a) : "l"(p));
    return a;
}
// remote (or self) store into cluster-peer shared memory
__device__ __forceinline__ void stc(uint32_t laddr, unsigned rank, float v) {
    uint32_t r;
    asm volatile("mapa.shared::cluster.u32 %0, %1, %2;" : "=r"(r) : "r"(laddr), "r"(rank));
    asm volatile("st.shared::cluster.f32 [%0], %1;" :: "r"(r), "f"(v) : "memory");
}
// release-arrive on rank's mbarrier (orders this thread's prior cluster stores)
__device__ __forceinline__ void arrive_rel(uint32_t lmbar, unsigned rank) {
    uint32_t r;
    asm volatile("mapa.shared::cluster.u32 %0, %1, %2;" : "=r"(r) : "r"(lmbar), "r"(rank));
    asm volatile("mbarrier.arrive.release.cluster.shared::cluster.b64 _, [%0];"
                 :: "r"(r) : "memory");
}
__device__ __forceinline__ void waitp(uint32_t mb, unsigned parity) {
    asm volatile(
        "{\n\t.reg .pred P;\n\t"
        "W1_%=:\n\t"
        "mbarrier.try_wait.parity.acquire.cluster.shared::cta.b64 P, [%0], %1, 0x989680;\n\t"
        "@P bra W2_%=;\n\t"
        "bra W1_%=;\n\t"
        "W2_%=:\n\t}"
        :: "r"(mb), "r"(parity) : "memory");
}

// ---------------- precompute GEMMs: C[4096,N] = X[4096,128] @ W[N,128]^T + bias (+bias2)
template <int N, int DEST>
__global__ __launch_bounds__(256) void gemm_bias(
    const float* __restrict__ X, const float* __restrict__ W,
    const float* __restrict__ bias, const float* __restrict__ bias2)
{
    constexpr int K = INN;  // 128
    __shared__ float As[32][64];  // k-major
    __shared__ float Bs[32][64];
    float* C = (DEST == 0) ? g_xg : g_bx;

    const int bm = blockIdx.y * 64, bn = blockIdx.x * 64;
    const int tid = threadIdx.x;
    const int tx = tid & 15, ty = tid >> 4;

    float acc[4][4];
#pragma unroll
    for (int r = 0; r < 4; r++)
#pragma unroll
        for (int c = 0; c < 4; c++) acc[r][c] = 0.f;

    for (int k0 = 0; k0 < K; k0 += 32) {
#pragma unroll
        for (int q = 0; q < 2; q++) {
            int i = tid * 2 + q;
            int row = i >> 3;
            int kc = (i & 7) * 4;
            float4 a = *(const float4*)(X + (size_t)(bm + row) * K + k0 + kc);
            As[kc + 0][row] = a.x; As[kc + 1][row] = a.y;
            As[kc + 2][row] = a.z; As[kc + 3][row] = a.w;
            float4 b = *(const float4*)(W + (size_t)(bn + row) * K + k0 + kc);
            Bs[kc + 0][row] = b.x; Bs[kc + 1][row] = b.y;
            Bs[kc + 2][row] = b.z; Bs[kc + 3][row] = b.w;
        }
        __syncthreads();
#pragma unroll
        for (int kk = 0; kk < 32; kk++) {
            float4 av = *(const float4*)&As[kk][ty * 4];
            float4 bv = *(const float4*)&Bs[kk][tx * 4];
            float ar[4] = {av.x, av.y, av.z, av.w};
            float br[4] = {bv.x, bv.y, bv.z, bv.w};
#pragma unroll
            for (int r = 0; r < 4; r++)
#pragma unroll
                for (int c = 0; c < 4; c++) acc[r][c] += ar[r] * br[c];
        }
        __syncthreads();
    }

    float bc[4];
#pragma unroll
    for (int c = 0; c < 4; c++) {
        bc[c] = bias[bn + tx * 4 + c];
        if (bias2) bc[c] += bias2[bn + tx * 4 + c];
    }
#pragma unroll
    for (int r = 0; r < 4; r++) {
        float4 o;
        o.x = acc[r][0] + bc[0]; o.y = acc[r][1] + bc[1];
        o.z = acc[r][2] + bc[2]; o.w = acc[r][3] + bc[3];
        *(float4*)(C + (size_t)(bm + ty * 4 + r) * N + bn + tx * 4) = o;
    }
}

// ---------------- weight repack for the 4-way cluster split -----------------
// seq access (rank c, thread tid):
//  whh: u2 idx = (c*16 + j)*1024 + tid, j in [0,16)
//       covers gate row grow = gq*256 + c*64 + hl (rl=tid>>2, gq=rl>>6, hl=rl&63),
//       k = (tid&3)*64 + j*4 .. +3
//  wa:  u2 idx = (c*4 + j)*1024 + tid,  j in [0,4)
//       row = c*64 + (tid>>4), k = (tid&15)*16 + j*4 .. +3
//  wc:  u2 idx = (c*2 + j)*1024 + tid,  j in [0,2)
//       row = c*32 + (tid>>5), k = (tid&31)*8 + j*4 .. +3
__global__ void pack_weights(const float* __restrict__ W_hh,
                             const float* __restrict__ W_A,
                             const float* __restrict__ W_C)
{
    int i = blockIdx.x * blockDim.x + threadIdx.x;
    if (i < G4 * HH) {
        int m = i & 3; int r = i >> 2;
        int tid = r & 1023; int cj = r >> 10; int j = cj & 15; int c = cj >> 4;
        int rl = tid >> 2, q = tid & 3;
        int gq = rl >> 6, hl = rl & 63;
        int grow = gq * HH + c * 64 + hl;
        g_whh_p[i] = W_hh[grow * HH + q * 64 + j * 4 + m];
    }
    if (i < HH * HH) {
        int m = i & 3; int r = i >> 2;
        int tid = r & 1023; int cj = r >> 10; int j = cj & 3; int c = cj >> 2;
        int rl = tid >> 4, q = tid & 15;
        g_wa_p[i] = W_A[(c * 64 + rl) * HH + q * 16 + j * 4 + m];
    }
    if (i < OO * HH) {
        int m = i & 3; int r = i >> 2;
        int tid = r & 1023; int cj = r >> 10; int j = cj & 1; int c = cj >> 1;
        int rl = tid >> 5, q = tid & 31;
        g_wc_p[i] = W_C[(c * 32 + rl) * HH + q * 8 + j * 4 + m];
    }
}

// ---------------- sequential fused kernel: 4-CTA cluster per batch ----------
__global__ __launch_bounds__(1024, 1) __cluster_dims__(4, 1, 1)
void seq_kernel(const float* __restrict__ timespans,  // [B,T]
                const float* __restrict__ tau,        // [H]
                const float* __restrict__ sigma,      // [H]
                const float* __restrict__ b_C,        // [OUT]
                float* __restrict__ out)              // [B,T,OUT]
{
    // full-vector exchange buffers (each rank owns 64 entries; peers fill rest)
    __shared__ __align__(16) float ex_h[HH];
    __shared__ __align__(16) float ex_u[HH];
    __shared__ __align__(16) float ex_us[HH];   // u / tau
    __shared__ __align__(16) float ex_fu[HH];   // tanh(u / sigma)
    __shared__ __align__(16) float ex_v1s[HH];  // v1 / tau
    __shared__ __align__(16) float sh_g[256];   // this rank's 256 gate rows
    __shared__ float sh_v1[64], sh_drv[64], sh_v2[64];
    __shared__ __align__(8) unsigned long long mbar[2];

    const int tid = threadIdx.x;
    const unsigned c = blockIdx.x & 3;       // cluster rank (== cluster_ctarank)
    const int b = blockIdx.x >> 2;           // batch

    if (tid < HH) { ex_h[tid] = 0.f; ex_u[tid] = 0.f; ex_us[tid] = 0.f;
                    ex_fu[tid] = 0.f; ex_v1s[tid] = 0.f; }
    const uint32_t mb1 = s2u(mbar), mb2 = mb1 + 8;
    if (tid == 0) {
        asm volatile("mbarrier.init.shared.b64 [%0], %1;" :: "r"(mb1), "r"(256u) : "memory");
        asm volatile("mbarrier.init.shared.b64 [%0], %1;" :: "r"(mb2), "r"(256u) : "memory");
    }
    __syncthreads();
    // publish mbarrier init + zeroed state cluster-wide before any remote op
    asm volatile("barrier.cluster.arrive.aligned;" ::: "memory");
    asm volatile("barrier.cluster.wait.aligned;" ::: "memory");

    // thread roles
    const int rlA = tid >> 2, qA = tid & 3;          // gate rows: 4 lanes/row
    const int gq = rlA >> 6, hl = rlA & 63;
    const int grow = gq * HH + c * 64 + hl;          // global gate row
    const int rlW = tid >> 4, qW = tid & 15;         // W_A rows: 16 lanes/row
    const int rlC = tid >> 5, qC = tid & 31;         // W_C rows: 32 lanes/row

    float itau_o = 0.f, isig_o = 0.f, u_reg = 0.f, c_reg = 0.f;
    if (tid < 64) {
        itau_o = 1.f / tau[c * 64 + tid];
        isig_o = 1.f / sigma[c * 64 + tid];
    }
    const float itau_w = 1.f / tau[c * 64 + rlW];    // used by qW==0 lanes
    const float bCr = b_C[c * 32 + rlC];

    const ulonglong2* whh = (const ulonglong2*)g_whh_p + (c * 16) * 1024 + tid;
    const ulonglong2* wap = (const ulonglong2*)g_wa_p + (c * 4) * 1024 + tid;
    const ulonglong2* wcp = (const ulonglong2*)g_wc_p + (c * 2) * 1024 + tid;
    const ulonglong2* hh2 = (const ulonglong2*)ex_h + qA * 16;
    const ulonglong2* us2 = (const ulonglong2*)ex_us + qW * 4;
    const ulonglong2* fu2 = (const ulonglong2*)ex_fu + qW * 4;
    const ulonglong2* v12 = (const ulonglong2*)ex_v1s + qW * 4;
    const ulonglong2* uu2 = (const ulonglong2*)ex_u + qC * 2;

    const uint32_t a_v1s = s2u(ex_v1s), a_h = s2u(ex_h), a_u = s2u(ex_u),
                   a_us = s2u(ex_us), a_fu = s2u(ex_fu);

    const float* xg_b = g_xg + (size_t)b * TT * G4;
    const float* bx_b = g_bx + (size_t)b * TT * HH;
    const float* ts_b = timespans + b * TT;
    float* out_b = out + (size_t)b * TT * OO;

    for (int t = 0; t < TT; t++) {
        const float ts = ts_b[t];
        const unsigned par = (unsigned)(t & 1);

        // ---- Phase A: 256 gate rows, dot(h_prev, W_hh row), 4 lanes/row ----
        {
            ull a0 = 0ull, a1 = 0ull;
#pragma unroll
            for (int j = 0; j < 16; j++) {
                ulonglong2 wv = whh[j * 1024];   // coalesced LDG.128
                ulonglong2 hv = hh2[j];          // broadcast LDS.128
                a0 = ffma2(a0, wv.x, hv.x);
                a1 = ffma2(a1, wv.y, hv.y);
            }
            float v = hsum2(a0) + hsum2(a1);
            v += __shfl_down_sync(0xffffffffu, v, 2, 4);
            v += __shfl_down_sync(0xffffffffu, v, 1, 4);
            if (qA == 0) sh_g[rlA] = v + xg_b[(size_t)t * G4 + grow];
        }
        // ---- Phase A2: v1 = ts*W_A@us, drv = W_A@fu (own 64 rows, 16 lanes/row)
        {
            ull av = 0ull, ad = 0ull;
#pragma unroll
            for (int j = 0; j < 4; j++) {
                ulonglong2 wv = wap[j * 1024];
                ulonglong2 uv = us2[j];
                ulonglong2 fv = fu2[j];
                av = ffma2(av, wv.x, uv.x); av = ffma2(av, wv.y, uv.y);
                ad = ffma2(ad, wv.x, fv.x); ad = ffma2(ad, wv.y, fv.y);
            }
            float v = hsum2(av), d = hsum2(ad);
#pragma unroll
            for (int o = 8; o >= 1; o >>= 1) {
                v += __shfl_down_sync(0xffffffffu, v, o, 16);
                d += __shfl_down_sync(0xffffffffu, d, o, 16);
            }
            if (qW == 0) {
                float v1 = ts * v;
                sh_v1[rlW] = v1;
                sh_drv[rlW] = d;
                float v1s = v1 * itau_w;
                uint32_t ad4 = a_v1s + (unsigned)(c * 64 + rlW) * 4;
#pragma unroll
                for (unsigned r = 0; r < 4; r++) stc(ad4, r, v1s);
#pragma unroll
                for (unsigned r = 0; r < 4; r++) arrive_rel(mb1, r);
            }
        }
        __syncthreads();   // sh_g / sh_v1 / sh_drv visible CTA-wide

        // ---- LSTM cell update (own 64 h) — overlapped with sync1 wait ----
        float bb = 0.f;
        if (tid < 64) {
            float gi = sh_g[tid], gf = sh_g[64 + tid];
            float gg = sh_g[128 + tid], go = sh_g[192 + tid];
            float si = 1.f / (1.f + __expf(-gi));
            float sf = 1.f / (1.f + __expf(-gf));
            float so = 1.f / (1.f + __expf(-go));
            c_reg = sf * c_reg + si * tanhf(gg);
            bb = so * tanhf(c_reg);
        }

        waitp(mb1, par);   // full ex_v1s available; all CTAs past Phase A/A2 reads

        if (tid < 64) {    // publish h_new (consumed at next step's Phase A)
            uint32_t ah = a_h + (unsigned)(c * 64 + tid) * 4;
#pragma unroll
            for (unsigned r = 0; r < 4; r++) stc(ah, r, bb);
        }

        // ---- v2 = W_A @ v1s (own 64 rows) ----
        {
            ull av = 0ull;
#pragma unroll
            for (int j = 0; j < 4; j++) {
                ulonglong2 wv = wap[j * 1024];
                ulonglong2 xv = v12[j];
                av = ffma2(av, wv.x, xv.x);
                av = ffma2(av, wv.y, xv.y);
            }
            float v = hsum2(av);
#pragma unroll
            for (int o = 8; o >= 1; o >>= 1)
                v += __shfl_down_sync(0xffffffffu, v, o, 16);
            if (qW == 0) sh_v2[rlW] = v;
        }
        __syncthreads();   // sh_v2 ready; also fences ex_v1s readers before C

        // ---- Phase C: ODE update (own 64 u), publish u/us/fu ----
        if (tid < 64) {
            float bx = bx_b[(size_t)t * HH + c * 64 + tid];
            float un = u_reg + sh_v1[tid] + 0.5f * ts * sh_v2[tid]
                     + ts * (sh_drv[tid] + bx) * itau_o + bb;
            u_reg = un;
            float us = un * itau_o;
            float fu = tanhf(un * isig_o);
            uint32_t off = (unsigned)(c * 64 + tid) * 4;
#pragma unroll
            for (unsigned r = 0; r < 4; r++) {
                stc(a_u + off, r, un);
                stc(a_us + off, r, us);
                stc(a_fu + off, r, fu);
            }
#pragma unroll
            for (unsigned r = 0; r < 4; r++) arrive_rel(mb2, r);
        }

        waitp(mb2, par);   // full ex_u/ex_us/ex_fu/ex_h available

        // ---- Phase D: y = u_new @ W_C^T + b_C (own 32 rows, 32 lanes/row) --
        {
            ull ay = 0ull;
#pragma unroll
            for (int j = 0; j < 2; j++) {
                ulonglong2 wv = wcp[j * 1024];
                ulonglong2 uv = uu2[j];
                ay = ffma2(ay, wv.x, uv.x);
                ay = ffma2(ay, wv.y, uv.y);
            }
            float y = hsum2(ay);
#pragma unroll
            for (int o = 16; o >= 1; o >>= 1)
                y += __shfl_down_sync(0xffffffffu, y, o, 32);
            if (qC == 0) out_b[(size_t)t * OO + c * 32 + rlC] = y + bCr;
        }
    }

    // no CTA may exit while peers' remote stores could still target its SMEM
    asm volatile("barrier.cluster.arrive.aligned;" ::: "memory");
    asm volatile("barrier.cluster.wait.aligned;" ::: "memory");
}

// ---------------- launch ----------------------------------------------------
extern "C" void kernel_launch(void* const* d_in, const int* in_sizes, int n_in,
                              void* d_out, int out_size)
{
    const float* x    = (const float*)d_in[0];   // [32,128,128]
    const float* tsp  = (const float*)d_in[1];   // [32,128]
    const float* tau  = (const float*)d_in[2];   // [256]
    const float* sig  = (const float*)d_in[3];   // [256]
    const float* W_A  = (const float*)d_in[4];   // [256,256]
    const float* W_B  = (const float*)d_in[5];   // [256,128]
    const float* b_B  = (const float*)d_in[6];   // [256]
    const float* W_C  = (const float*)d_in[7];   // [128,256]
    const float* b_C  = (const float*)d_in[8];   // [128]
    const float* W_ih = (const float*)d_in[9];   // [1024,128]
    const float* W_hh = (const float*)d_in[10];  // [1024,256]
    const float* b_ih = (const float*)d_in[11];  // [1024]
    const float* b_hh = (const float*)d_in[12];  // [1024]
    float* out = (float*)d_out;                  // [32,128,128]

    pack_weights<<<(G4 * HH + 255) / 256, 256>>>(W_hh, W_A, W_C);

    gemm_bias<G4, 0><<<dim3(G4 / 64, (BB * TT) / 64), 256>>>(x, W_ih, b_ih, b_hh);
    gemm_bias<HH, 1><<<dim3(HH / 64, (BB * TT) / 64), 256>>>(x, W_B, b_B, nullptr);

    // 32 batches x 4-CTA clusters = 128 CTAs
    seq_kernel<<<BB * 4, 1024>>>(tsp, tau, sig, b_C, out);
}

// round 9
// speedup vs baseline: 2.5302x; 1.2992x over previous
#include <cuda_runtime.h>
#include <cuda_fp16.h>
#include <cstdint>

// Sizes (fixed by the problem)
#define BB   32
#define TT   128
#define INN  128
#define HH   256
#define G4   1024   // 4*HH
#define OO   128

// ---------------- scratch (__device__ globals: no runtime allocation) -------
static __device__ __align__(16) float g_xg[BB * TT * G4];   // xg = x@W_ih^T + b_ih + b_hh
static __device__ __align__(16) float g_bx[BB * TT * HH];   // Bx = x@W_B^T + b_B
static __device__ __align__(16) __half g_whh_h[G4 * HH];    // W_hh fp16, 4-way split layout
static __device__ __align__(16) float g_wa_p[HH * HH];      // W_A fp32 repack
static __device__ __align__(16) float g_m2_p[HH * HH];      // M2 = W_A*D*W_A fp32 repack
static __device__ __align__(16) float g_m2f[HH * HH];       // M2 row-major intermediate
static __device__ __align__(16) float g_wc_p[OO * HH];      // W_C fp32 repack

typedef unsigned long long ull;

__device__ __forceinline__ ull ffma2(ull c, ull a, ull b) {
    ull d;
    asm("fma.rn.f32x2 %0, %1, %2, %3;" : "=l"(d) : "l"(a), "l"(b), "l"(c));
    return d;
}
__device__ __forceinline__ float hsum2(ull v) {
    return __uint_as_float((unsigned)(v & 0xffffffffull)) +
           __uint_as_float((unsigned)(v >> 32));
}
__device__ __forceinline__ ull packf2(float x, float y) {
    ull r; asm("mov.b64 %0, {%1, %2};" : "=l"(r) : "f"(x), "f"(y)); return r;
}
// half2 (as 32 bits) -> packed f32x2
__device__ __forceinline__ ull h2f2(unsigned h2bits) {
    __half2 h = *reinterpret_cast<const __half2*>(&h2bits);
    float2 f = __half22float2(h);
    return packf2(f.x, f.y);
}
// 16B L2-only load (protect L1 residency of W_hh)
__device__ __forceinline__ ulonglong2 ldcg16(const void* p) {
    float4 t = __ldcg((const float4*)p);
    ulonglong2 r; r.x = packf2(t.x, t.y); r.y = packf2(t.z, t.w);
    return r;
}
__device__ __forceinline__ uint32_t s2u(const void* p) {
    uint32_t a;
    asm("{ .reg .u64 t; cvta.to.shared.u64 t, %1; cvt.u32.u64 %0, t; }"
        : "=r"(a) : "l"(p));
    return a;
}
__device__ __forceinline__ void stc(uint32_t laddr, unsigned rank, float v) {
    uint32_t r;
    asm volatile("mapa.shared::cluster.u32 %0, %1, %2;" : "=r"(r) : "r"(laddr), "r"(rank));
    asm volatile("st.shared::cluster.f32 [%0], %1;" :: "r"(r), "f"(v) : "memory");
}
__device__ __forceinline__ void arrive_rel(uint32_t lmbar, unsigned rank) {
    uint32_t r;
    asm volatile("mapa.shared::cluster.u32 %0, %1, %2;" : "=r"(r) : "r"(lmbar), "r"(rank));
    asm volatile("mbarrier.arrive.release.cluster.shared::cluster.b64 _, [%0];"
                 :: "r"(r) : "memory");
}
__device__ __forceinline__ void waitp(uint32_t mb, unsigned parity) {
    asm volatile(
        "{\n\t.reg .pred P;\n\t"
        "W1_%=:\n\t"
        "mbarrier.try_wait.parity.acquire.cluster.shared::cta.b64 P, [%0], %1, 0x989680;\n\t"
        "@P bra W2_%=;\n\t"
        "bra W1_%=;\n\t"
        "W2_%=:\n\t}"
        :: "r"(mb), "r"(parity) : "memory");
}

// ---------------- M2 = W_A * diag(1/tau) * W_A  (fp32, one-time) ------------
__global__ __launch_bounds__(256) void compute_m2(const float* __restrict__ W_A,
                                                  const float* __restrict__ tau)
{
    __shared__ float ai[HH];
    const int i = blockIdx.x, j = threadIdx.x;
    ai[j] = W_A[i * HH + j] / tau[j];
    __syncthreads();
    float acc = 0.f;
    for (int k = 0; k < HH; k++)
        acc += ai[k] * W_A[k * HH + j];
    g_m2f[i * HH + j] = acc;
}

// ---------------- precompute GEMMs: C[4096,N] = X[4096,128] @ W[N,128]^T + bias (+bias2)
template <int N, int DEST>
__global__ __launch_bounds__(256) void gemm_bias(
    const float* __restrict__ X, const float* __restrict__ W,
    const float* __restrict__ bias, const float* __restrict__ bias2)
{
    constexpr int K = INN;  // 128
    __shared__ float As[32][64];
    __shared__ float Bs[32][64];
    float* C = (DEST == 0) ? g_xg : g_bx;

    const int bm = blockIdx.y * 64, bn = blockIdx.x * 64;
    const int tid = threadIdx.x;
    const int tx = tid & 15, ty = tid >> 4;

    float acc[4][4];
#pragma unroll
    for (int r = 0; r < 4; r++)
#pragma unroll
        for (int c = 0; c < 4; c++) acc[r][c] = 0.f;

    for (int k0 = 0; k0 < K; k0 += 32) {
#pragma unroll
        for (int q = 0; q < 2; q++) {
            int i = tid * 2 + q;
            int row = i >> 3;
            int kc = (i & 7) * 4;
            float4 a = *(const float4*)(X + (size_t)(bm + row) * K + k0 + kc);
            As[kc + 0][row] = a.x; As[kc + 1][row] = a.y;
            As[kc + 2][row] = a.z; As[kc + 3][row] = a.w;
            float4 b = *(const float4*)(W + (size_t)(bn + row) * K + k0 + kc);
            Bs[kc + 0][row] = b.x; Bs[kc + 1][row] = b.y;
            Bs[kc + 2][row] = b.z; Bs[kc + 3][row] = b.w;
        }
        __syncthreads();
#pragma unroll
        for (int kk = 0; kk < 32; kk++) {
            float4 av = *(const float4*)&As[kk][ty * 4];
            float4 bv = *(const float4*)&Bs[kk][tx * 4];
            float ar[4] = {av.x, av.y, av.z, av.w};
            float br[4] = {bv.x, bv.y, bv.z, bv.w};
#pragma unroll
            for (int r = 0; r < 4; r++)
#pragma unroll
                for (int c = 0; c < 4; c++) acc[r][c] += ar[r] * br[c];
        }
        __syncthreads();
    }

    float bc[4];
#pragma unroll
    for (int c = 0; c < 4; c++) {
        bc[c] = bias[bn + tx * 4 + c];
        if (bias2) bc[c] += bias2[bn + tx * 4 + c];
    }
#pragma unroll
    for (int r = 0; r < 4; r++) {
        float4 o;
        o.x = acc[r][0] + bc[0]; o.y = acc[r][1] + bc[1];
        o.z = acc[r][2] + bc[2]; o.w = acc[r][3] + bc[3];
        *(float4*)(C + (size_t)(bm + ty * 4 + r) * N + bn + tx * 4) = o;
    }
}

// ---------------- weight repack ---------------------------------------------
// whh (fp16): half idx i: m=i&7, u=i>>3, tid=u&1023, cj=u>>10, j=cj&7, c=cj>>3
//   rl=tid>>2, q=tid&3, gq=rl>>6, hl=rl&63, grow=gq*256+c*64+hl, k=q*64+j*8+m
// wa/m2 (fp32): m=i&3, r=i>>2, tid=r&1023, cj=r>>10, j=cj&3, c=cj>>2
//   row=c*64+(tid>>4), k=(tid&15)*16+j*4+m
// wc (fp32): m=i&3, r=i>>2, tid=r&1023, cj=r>>10, j=cj&1, c=cj>>1
//   row=c*32+(tid>>5), k=(tid&31)*8+j*4+m
__global__ void pack_weights(const float* __restrict__ W_hh,
                             const float* __restrict__ W_A,
                             const float* __restrict__ W_C)
{
    int i = blockIdx.x * blockDim.x + threadIdx.x;
    if (i < G4 * HH) {  // fp16 whh
        int m = i & 7; int u = i >> 3;
        int tid = u & 1023; int cj = u >> 10; int j = cj & 7; int c = cj >> 3;
        int rl = tid >> 2, q = tid & 3;
        int gq = rl >> 6, hl = rl & 63;
        int grow = gq * HH + c * 64 + hl;
        g_whh_h[i] = __float2half(W_hh[grow * HH + q * 64 + j * 8 + m]);
    }
    if (i < HH * HH) {
        int m = i & 3; int r = i >> 2;
        int tid = r & 1023; int cj = r >> 10; int j = cj & 3; int c = cj >> 2;
        int rl = tid >> 4, q = tid & 15;
        int src = (c * 64 + rl) * HH + q * 16 + j * 4 + m;
        g_wa_p[i] = W_A[src];
        g_m2_p[i] = g_m2f[src];
    }
    if (i < OO * HH) {
        int m = i & 3; int r = i >> 2;
        int tid = r & 1023; int cj = r >> 10; int j = cj & 1; int c = cj >> 1;
        int rl = tid >> 5, q = tid & 31;
        g_wc_p[i] = W_C[(c * 32 + rl) * HH + q * 8 + j * 4 + m];
    }
}

// ---------------- sequential fused kernel: 4-CTA cluster per batch ----------
// One __syncthreads + ONE cluster exchange per step (double-buffered state).
__global__ __launch_bounds__(1024, 1) __cluster_dims__(4, 1, 1)
void seq_kernel(const float* __restrict__ timespans,  // [B,T]
                const float* __restrict__ tau,        // [H]
                const float* __restrict__ sigma,      // [H]
                const float* __restrict__ b_C,        // [OUT]
                float* __restrict__ out)              // [B,T,OUT]
{
    __shared__ __align__(16) float ex_h[2][HH];
    __shared__ __align__(16) float ex_u[2][HH];
    __shared__ __align__(16) float ex_us[2][HH];   // u / tau
    __shared__ __align__(16) float ex_fu[2][HH];   // tanh(u / sigma)
    __shared__ __align__(16) float sh_g[256];      // this rank's 256 gate rows
    __shared__ float sh_v1[64], sh_drv[64], sh_v2[64];
    __shared__ __align__(8) unsigned long long mbar[2];

    const int tid = threadIdx.x;
    const unsigned c = blockIdx.x & 3;       // cluster rank
    const int b = blockIdx.x >> 2;           // batch

    if (tid < HH) {
#pragma unroll
        for (int p = 0; p < 2; p++) {
            ex_h[p][tid] = 0.f; ex_u[p][tid] = 0.f;
            ex_us[p][tid] = 0.f; ex_fu[p][tid] = 0.f;
        }
    }
    const uint32_t mb0 = s2u(mbar);
    if (tid == 0) {
        asm volatile("mbarrier.init.shared.b64 [%0], %1;" :: "r"(mb0), "r"(256u) : "memory");
        asm volatile("mbarrier.init.shared.b64 [%0], %1;" :: "r"(mb0 + 8), "r"(256u) : "memory");
    }
    __syncthreads();
    asm volatile("barrier.cluster.arrive.aligned;" ::: "memory");
    asm volatile("barrier.cluster.wait.aligned;" ::: "memory");

    // thread roles
    const int rlA = tid >> 2, qA = tid & 3;          // gate rows: 4 lanes/row
    const int gq = rlA >> 6, hl = rlA & 63;
    const int grow = gq * HH + c * 64 + hl;          // global gate row
    const int rlW = tid >> 4, qW = tid & 15;         // W_A/M2 rows: 16 lanes/row
    const int rlC = tid >> 5, qC = tid & 31;         // W_C rows: 32 lanes/row

    float itau_o = 0.f, isig_o = 0.f, u_reg = 0.f, c_reg = 0.f;
    if (tid < 64) {
        itau_o = 1.f / tau[c * 64 + tid];
        isig_o = 1.f / sigma[c * 64 + tid];
    }
    const float bCr = b_C[c * 32 + rlC];

    const ulonglong2* whh16 = (const ulonglong2*)g_whh_h + (c * 8) * 1024 + tid;
    const float* wap = g_wa_p + ((c * 4) * 1024 + tid) * 4;
    const float* m2p = g_m2_p + ((c * 4) * 1024 + tid) * 4;
    const float* wcp = g_wc_p + ((c * 2) * 1024 + tid) * 4;

    const uint32_t a_h[2]  = { s2u(ex_h[0]),  s2u(ex_h[1])  };
    const uint32_t a_u[2]  = { s2u(ex_u[0]),  s2u(ex_u[1])  };
    const uint32_t a_us[2] = { s2u(ex_us[0]), s2u(ex_us[1]) };
    const uint32_t a_fu[2] = { s2u(ex_fu[0]), s2u(ex_fu[1]) };

    const float* xg_b = g_xg + (size_t)b * TT * G4;
    const float* bx_b = g_bx + (size_t)b * TT * HH;
    const float* ts_b = timespans + b * TT;
    float* out_b = out + (size_t)b * TT * OO;

    for (int t = 0; t < TT; t++) {
        const int p = t & 1, pn = p ^ 1;
        const unsigned par = (unsigned)((t >> 1) & 1);
        const float ts = ts_b[t];

        // ---- Phase A: 256 gate rows, dot(h_prev, W_hh row) fp16, 4 lanes/row
        {
            const ulonglong2* hh = (const ulonglong2*)&ex_h[p][qA * 64];
            ull a0 = 0ull, a1 = 0ull;
#pragma unroll
            for (int j = 0; j < 8; j++) {
                ulonglong2 wv = whh16[j * 1024];   // L1-resident LDG.128 (8 halves)
                ulonglong2 h0 = hh[2 * j];
                ulonglong2 h1 = hh[2 * j + 1];
                a0 = ffma2(a0, h2f2((unsigned)wv.x),         h0.x);
                a1 = ffma2(a1, h2f2((unsigned)(wv.x >> 32)), h0.y);
                a0 = ffma2(a0, h2f2((unsigned)wv.y),         h1.x);
                a1 = ffma2(a1, h2f2((unsigned)(wv.y >> 32)), h1.y);
            }
            float v = hsum2(a0) + hsum2(a1);
            v += __shfl_down_sync(0xffffffffu, v, 2, 4);
            v += __shfl_down_sync(0xffffffffu, v, 1, 4);
            if (qA == 0) sh_g[rlA] = v + __ldcg(&xg_b[(size_t)t * G4 + grow]);
        }

        // ---- Phase A2: v1 = ts*W_A@us, drv = W_A@fu, v2 = ts*M2@us (local!)
        {
            const ulonglong2* us2 = (const ulonglong2*)&ex_us[p][qW * 16];
            const ulonglong2* fu2 = (const ulonglong2*)&ex_fu[p][qW * 16];
            ull av = 0ull, ad = 0ull, a2 = 0ull;
#pragma unroll
            for (int j = 0; j < 4; j++) {
                ulonglong2 wv = ldcg16(wap + j * 4096);   // L2-only
                ulonglong2 mv = ldcg16(m2p + j * 4096);   // L2-only
                ulonglong2 uv = us2[j];
                ulonglong2 fv = fu2[j];
                av = ffma2(av, wv.x, uv.x); av = ffma2(av, wv.y, uv.y);
                ad = ffma2(ad, wv.x, fv.x); ad = ffma2(ad, wv.y, fv.y);
                a2 = ffma2(a2, mv.x, uv.x); a2 = ffma2(a2, mv.y, uv.y);
            }
            float v = hsum2(av), d = hsum2(ad), w = hsum2(a2);
#pragma unroll
            for (int o = 8; o >= 1; o >>= 1) {
                v += __shfl_down_sync(0xffffffffu, v, o, 16);
                d += __shfl_down_sync(0xffffffffu, d, o, 16);
                w += __shfl_down_sync(0xffffffffu, w, o, 16);
            }
            if (qW == 0) {
                sh_v1[rlW] = ts * v;
                sh_drv[rlW] = d;
                sh_v2[rlW] = ts * w;     // = A_eff @ v1  (via M2)
            }
        }
        __syncthreads();   // sh_g / sh_v1 / sh_drv / sh_v2 visible CTA-wide

        // ---- LSTM cell + ODE update (own 64 lanes), publish state ----
        if (tid < 64) {
            float gi = sh_g[tid], gf = sh_g[64 + tid];
            float gg = sh_g[128 + tid], go = sh_g[192 + tid];
            float si = 1.f / (1.f + __expf(-gi));
            float sf = 1.f / (1.f + __expf(-gf));
            float so = 1.f / (1.f + __expf(-go));
            c_reg = sf * c_reg + si * tanhf(gg);
            float bb = so * tanhf(c_reg);

            float bx = __ldcg(&bx_b[(size_t)t * HH + c * 64 + tid]);
            float un = u_reg + sh_v1[tid] + 0.5f * ts * sh_v2[tid]
                     + ts * (sh_drv[tid] + bx) * itau_o + bb;
            u_reg = un;
            float us = un * itau_o;
            float fu = tanhf(un * isig_o);

            const uint32_t off = (unsigned)(c * 64 + tid) * 4;
#pragma unroll
            for (unsigned r = 0; r < 4; r++) {
                stc(a_u[pn] + off, r, un);
                stc(a_us[pn] + off, r, us);
                stc(a_fu[pn] + off, r, fu);
                stc(a_h[pn] + off, r, bb);
            }
#pragma unroll
            for (unsigned r = 0; r < 4; r++) arrive_rel(mb0 + (unsigned)p * 8, r);
        }

        waitp(mb0 + (unsigned)p * 8, par);   // full u/us/fu/h of this step available

        // ---- Phase D: y = u_new @ W_C^T + b_C (own 32 rows, 32 lanes/row) --
        {
            const ulonglong2* uu = (const ulonglong2*)&ex_u[pn][qC * 8];
            ull ay = 0ull;
#pragma unroll
            for (int j = 0; j < 2; j++) {
                ulonglong2 wv = ldcg16(wcp + j * 4096);
                ulonglong2 uv = uu[j];
                ay = ffma2(ay, wv.x, uv.x);
                ay = ffma2(ay, wv.y, uv.y);
            }
            float y = hsum2(ay);
#pragma unroll
            for (int o = 16; o >= 1; o >>= 1)
                y += __shfl_down_sync(0xffffffffu, y, o, 32);
            if (qC == 0) out_b[(size_t)t * OO + c * 32 + rlC] = y + bCr;
        }
    }

    // no CTA may exit while peers' remote stores could still target its SMEM
    asm volatile("barrier.cluster.arrive.aligned;" ::: "memory");
    asm volatile("barrier.cluster.wait.aligned;" ::: "memory");
}

// ---------------- launch ----------------------------------------------------
extern "C" void kernel_launch(void* const* d_in, const int* in_sizes, int n_in,
                              void* d_out, int out_size)
{
    const float* x    = (const float*)d_in[0];   // [32,128,128]
    const float* tsp  = (const float*)d_in[1];   // [32,128]
    const float* tau  = (const float*)d_in[2];   // [256]
    const float* sig  = (const float*)d_in[3];   // [256]
    const float* W_A  = (const float*)d_in[4];   // [256,256]
    const float* W_B  = (const float*)d_in[5];   // [256,128]
    const float* b_B  = (const float*)d_in[6];   // [256]
    const float* W_C  = (const float*)d_in[7];   // [128,256]
    const float* b_C  = (const float*)d_in[8];   // [128]
    const float* W_ih = (const float*)d_in[9];   // [1024,128]
    const float* W_hh = (const float*)d_in[10];  // [1024,256]
    const float* b_ih = (const float*)d_in[11];  // [1024]
    const float* b_hh = (const float*)d_in[12];  // [1024]
    float* out = (float*)d_out;                  // [32,128,128]

    // M2 = W_A * diag(1/tau) * W_A, then repack all weights
    compute_m2<<<HH, HH>>>(W_A, tau);
    pack_weights<<<(G4 * HH + 255) / 256, 256>>>(W_hh, W_A, W_C);

    gemm_bias<G4, 0><<<dim3(G4 / 64, (BB * TT) / 64), 256>>>(x, W_ih, b_ih, b_hh);
    gemm_bias<HH, 1><<<dim3(HH / 64, (BB * TT) / 64), 256>>>(x, W_B, b_B, nullptr);

    // 32 batches x 4-CTA clusters = 128 CTAs
    seq_kernel<<<BB * 4, 1024>>>(tsp, sig ? tau : tau, sig, b_C, out);
}